// round 11
// baseline (speedup 1.0000x reference)
#include <cuda_runtime.h>
#include <cstdint>
#include <math.h>

#define BB 8
#define CC 8
#define HH 256
#define WW 512
#define PLANE (HH*WW)
#define NPIX (BB*PLANE)
#define BANDH 8
#define NROWS (BANDH+2)
#define TX 128                            /* cols per iter CTA */
#define SROW 136                          /* smem row stride: 4-col halo pad each side */
#define GRID_I (BB*(HH/BANDH)*(WW/TX))    /* 8*32*4 = 1024 */
#define NITER 16

#define CHUNKS_PER_ROW (SROW/4)           /* 34 x 16B */
#define GCH (CC*NROWS*CHUNKS_PER_ROW)     /* 2720 */
#define DCH (NROWS*CHUNKS_PER_ROW)        /* 340 */
#define SMEM_FLOATS (CC*NROWS*SROW + NROWS*SROW + CC*BANDH*TX)
#define SMEM_BYTES (SMEM_FLOATS*4)        /* 81,728 B */

// Depth ping-pong scratch (allocation-free).
__device__ float d_bufA[NPIX];            // 4 MB
__device__ float d_bufB[NPIX];            // 4 MB

__device__ __forceinline__ void cp16(unsigned int dst_smem, const float* src) {
    asm volatile("cp.async.ca.shared.global [%0], [%1], 16;\n"
                 :: "r"(dst_smem), "l"(src));
}

// ---------------------------------------------------------------------------
// Init: d0 = sparse > 0 ? sparse : blur   (pure elementwise)
// ---------------------------------------------------------------------------
__global__ __launch_bounds__(256) void init_kernel(
    const float* __restrict__ blur,
    const float* __restrict__ sparse)
{
    const int i = blockIdx.x * 256 + threadIdx.x;   // float4 index
    const float4 s = reinterpret_cast<const float4*>(sparse)[i];
    float4 v       = reinterpret_cast<const float4*>(blur)[i];
    v.x = (s.x > 0.f) ? s.x : v.x;
    v.y = (s.y > 0.f) ? s.y : v.y;
    v.z = (s.z > 0.f) ? s.z : v.z;
    v.w = (s.w > 0.f) ? s.w : v.w;
    reinterpret_cast<float4*>(d_bufA)[i] = v;
}

// ---------------------------------------------------------------------------
// One CSPN step:
//   d_new(p) = max_c [ sum_{3x3} g_c(n) d(n) / sum_{3x3} g_c(n) ],  g = |guid|
//   then sparse re-injection.
// cp.async stages all 8 g bands + the d band (halo-padded) into smem once;
// the mainloop is purely smem-fed (2 LDS.128 + 4 scalar LDS per row), with
// boundary handling via clamped copy addresses + fp masks. No shuffles, no
// divergent branches, no register-resident load pipeline.
// ---------------------------------------------------------------------------
__global__ __launch_bounds__(256, 2) void iter_kernel(
    int src_sel,                    // 0: read d_bufA, 1: read d_bufB
    float* __restrict__ dst_ext,    // if non-null, write here (final iter)
    const float* __restrict__ guid,
    const float* __restrict__ sparse)
{
    extern __shared__ float smem[];
    float* sg   = smem;                          // [CC][NROWS][SROW]
    float* sd   = sg + CC * NROWS * SROW;        // [NROWS][SROW]
    float* sout = sd + NROWS * SROW;             // [CC][BANDH][TX]

    const int tid  = threadIdx.x;
    const int lane = tid & 31;
    const int c    = tid >> 5;             // warp == channel
    const int bid  = blockIdx.x;
    const int xc   = bid & 3;
    const int yb   = (bid >> 2) & 31;
    const int b    = bid >> 7;
    const int x0   = xc * TX;
    const int y0   = yb * BANDH;

    const float* dsrc = src_sel ? d_bufB : d_bufA;
    float*       ddst = dst_ext ? dst_ext : (src_sel ? d_bufA : d_bufB);
    const float* dsb  = dsrc   + (size_t)b * PLANE;
    const float* spb  = sparse + (size_t)b * PLANE;
    float*       ddb  = ddst   + (size_t)b * PLANE;
    const float* gbase = guid + ((size_t)(b * CC)) * PLANE;

    // ---- cp.async prologue: stage g bands + d band into smem ----
    #pragma unroll 1
    for (int idx = tid; idx < GCH + DCH; idx += 256) {
        int row, j;
        const float* src;
        unsigned int dst;
        if (idx < GCH) {
            const int cc  = idx / (NROWS * CHUNKS_PER_ROW);
            const int rem = idx - cc * (NROWS * CHUNKS_PER_ROW);
            row = rem / CHUNKS_PER_ROW;
            j   = rem - row * CHUNKS_PER_ROW;
            const int ry  = y0 - 1 + row;
            const int ryc = (ry < 0) ? 0 : ((ry >= HH) ? (HH - 1) : ry);
            int c0 = x0 - 4 + 4 * j;
            c0 = (c0 < 0) ? 0 : ((c0 > WW - 4) ? (WW - 4) : c0);
            src = gbase + (size_t)cc * PLANE + (size_t)ryc * WW + c0;
            dst = (unsigned int)__cvta_generic_to_shared(sg + (cc * NROWS + row) * SROW + 4 * j);
        } else {
            const int t = idx - GCH;
            row = t / CHUNKS_PER_ROW;
            j   = t - row * CHUNKS_PER_ROW;
            const int ry  = y0 - 1 + row;
            const int ryc = (ry < 0) ? 0 : ((ry >= HH) ? (HH - 1) : ry);
            int c0 = x0 - 4 + 4 * j;
            c0 = (c0 < 0) ? 0 : ((c0 > WW - 4) ? (WW - 4) : c0);
            src = dsb + (size_t)ryc * WW + c0;
            dst = (unsigned int)__cvta_generic_to_shared(sd + row * SROW + 4 * j);
        }
        cp16(dst, src);
    }
    asm volatile("cp.async.commit_group;\n" ::: "memory");

    // ---- prefetch sparse for the epilogue while cp.async is in flight ----
    const int ep_row = tid >> 5;           // 0..7
    const int ep_c4  = tid & 31;
    const float4 sp_pre = *reinterpret_cast<const float4*>(
                              spb + (size_t)(y0 + ep_row) * WW + x0 + ep_c4 * 4);

    asm volatile("cp.async.wait_group 0;\n" ::: "memory");
    __syncthreads();

    // ---- this warp's channel: smem-fed mainloop, rolling vertical sums ----
    const float* sgc = sg + c * NROWS * SROW;
    // per-lane edge masks (only the true image border is masked out)
    const float lm = (lane == 0)  ? ((x0 > 0)       ? 1.f : 0.f) : 1.f;
    const float rm = (lane == 31) ? ((x0 + TX < WW) ? 1.f : 0.f) : 1.f;
    const int   sc = 4 + lane * 4;         // smem col of this lane's vec4

    float4 usp = make_float4(0.f,0.f,0.f,0.f), usc = usp;  // u = g*d rowsums
    float4 gsp = make_float4(0.f,0.f,0.f,0.f), gsc = gsp;  // g rowsums

    #pragma unroll
    for (int i = 0; i < NROWS; i++) {
        const int   ry    = y0 - 1 + i;
        const float vmask = (ry >= 0 && ry < HH) ? 1.f : 0.f;

        const float* gp = sgc + i * SROW + sc;
        const float* dp = sd  + i * SROW + sc;
        const float4 gr = *reinterpret_cast<const float4*>(gp);
        const float4 dr = *reinterpret_cast<const float4*>(dp);
        const float  gL = gp[-1], gR = gp[4];
        const float  dL = dp[-1], dR = dp[4];

        float4 ga;
        ga.x = fabsf(gr.x) * vmask; ga.y = fabsf(gr.y) * vmask;
        ga.z = fabsf(gr.z) * vmask; ga.w = fabsf(gr.w) * vmask;
        const float gm1 = fabsf(gL) * (vmask * lm);
        const float gp4 = fabsf(gR) * (vmask * rm);

        const float um1 = gm1  * dL;
        const float u0  = ga.x * dr.x;
        const float u1  = ga.y * dr.y;
        const float u2  = ga.z * dr.z;
        const float u3  = ga.w * dr.w;
        const float up4 = gp4  * dR;

        float4 usn, gsn;
        {
            const float t01 = u0 + u1, t12 = u1 + u2, t23 = u2 + u3;
            usn.x = um1 + t01; usn.y = t01 + u2;
            usn.z = t12 + u3;  usn.w = t23 + up4;
            const float s01 = ga.x + ga.y, s12 = ga.y + ga.z, s23 = ga.z + ga.w;
            gsn.x = gm1 + s01;  gsn.y = s01 + ga.z;
            gsn.z = s12 + ga.w; gsn.w = s23 + gp4;
        }

        if (i >= 2) {
            float4 o;
            o.x = __fdividef(usp.x + usc.x + usn.x, gsp.x + gsc.x + gsn.x);
            o.y = __fdividef(usp.y + usc.y + usn.y, gsp.y + gsc.y + gsn.y);
            o.z = __fdividef(usp.z + usc.z + usn.z, gsp.z + gsc.z + gsn.z);
            o.w = __fdividef(usp.w + usc.w + usn.w, gsp.w + gsc.w + gsn.w);
            *reinterpret_cast<float4*>(sout + ((c * BANDH + (i - 2)) * TX) + lane * 4) = o;
        }
        usp = usc; usc = usn;
        gsp = gsc; gsc = gsn;
    }
    __syncthreads();

    // ---- 8-way max reduce + sparse re-injection + float4 store ----
    {
        const float* so = sout + ep_row * TX + ep_c4 * 4;
        float4 m = *reinterpret_cast<const float4*>(so);
        #pragma unroll
        for (int cc = 1; cc < CC; cc++) {
            const float4 v = *reinterpret_cast<const float4*>(so + cc * BANDH * TX);
            m.x = fmaxf(m.x, v.x); m.y = fmaxf(m.y, v.y);
            m.z = fmaxf(m.z, v.z); m.w = fmaxf(m.w, v.w);
        }
        m.x = (sp_pre.x > 0.f) ? sp_pre.x : m.x;
        m.y = (sp_pre.y > 0.f) ? sp_pre.y : m.y;
        m.z = (sp_pre.z > 0.f) ? sp_pre.z : m.z;
        m.w = (sp_pre.w > 0.f) ? sp_pre.w : m.w;
        *reinterpret_cast<float4*>(ddb + (size_t)(y0 + ep_row) * WW + x0 + ep_c4 * 4) = m;
    }
}

extern "C" void kernel_launch(void* const* d_in, const int* in_sizes, int n_in,
                              void* d_out, int out_size)
{
    const float* guid   = (const float*)d_in[0];
    const float* blur   = (const float*)d_in[1];
    const float* sparse = (const float*)d_in[2];
    float*       out    = (float*)d_out;

    static int attr_done = 0;
    if (!attr_done) {
        cudaFuncSetAttribute(iter_kernel,
                             cudaFuncAttributeMaxDynamicSharedMemorySize,
                             SMEM_BYTES);
        attr_done = 1;
    }

    init_kernel<<<NPIX / 4 / 256, 256>>>(blur, sparse);

    // d0 lives in d_bufA. Even i reads A writes B, odd i reads B writes A.
    for (int i = 0; i < NITER; i++) {
        float* dst_ext = (i == NITER - 1) ? out : nullptr;
        iter_kernel<<<GRID_I, 256, SMEM_BYTES>>>(i & 1, dst_ext, guid, sparse);
    }
}

// round 12
// speedup vs baseline: 1.1964x; 1.1964x over previous
#include <cuda_runtime.h>
#include <cstdint>
#include <math.h>

#define BB 8
#define CC 8
#define HH 256
#define WW 512
#define PLANE (HH*WW)
#define NPIX (BB*PLANE)
#define BANDH 8
#define NROWS (BANDH+2)
#define TX 128                            /* output cols per CTA */
#define SROW 136                          /* smem row stride (4-col pad each side) */
#define GRID_I (BB*(HH/BANDH)*(WW/TX))    /* 1024 */
#define NITER 16
#define FULLMASK 0xffffffffu

#define SG_FLOATS (CC*NROWS*SROW)         /* 10880 */
#define SD_FLOATS (NROWS*SROW)            /* 1360  */
#define SOUT_FLOATS (CC*BANDH*TX)         /* 8192  */
#define SMEM_FLOATS (16 + SG_FLOATS + SD_FLOATS + SOUT_FLOATS)
#define SMEM_BYTES (SMEM_FLOATS*4)        /* 81792 B */

// Depth ping-pong scratch (allocation-free).
__device__ float d_bufA[NPIX];            // 4 MB
__device__ float d_bufB[NPIX];            // 4 MB

// ---------------------------------------------------------------------------
// Init: d0 = sparse > 0 ? sparse : blur   (pure elementwise)
// ---------------------------------------------------------------------------
__global__ __launch_bounds__(256) void init_kernel(
    const float* __restrict__ blur,
    const float* __restrict__ sparse)
{
    const int i = blockIdx.x * 256 + threadIdx.x;   // float4 index
    const float4 s = reinterpret_cast<const float4*>(sparse)[i];
    float4 v       = reinterpret_cast<const float4*>(blur)[i];
    v.x = (s.x > 0.f) ? s.x : v.x;
    v.y = (s.y > 0.f) ? s.y : v.y;
    v.z = (s.z > 0.f) ? s.z : v.z;
    v.w = (s.w > 0.f) ? s.w : v.w;
    reinterpret_cast<float4*>(d_bufA)[i] = v;
}

// ---------------------------------------------------------------------------
// One CSPN step:
//   d_new(p) = max_c [ sum_{3x3} g_c(n) d(n) / sum_{3x3} g_c(n) ],  g = |guid|
//   then sparse re-injection.
// 90 cp.async.bulk row copies stage all 8 g bands + the d band into smem
// (one instruction per row, mbarrier complete_tx). Mainloop is the round-9
// rolling structure fed from smem: 2 LDS.128 + 4 broadcast LDS + 4 shfl per
// row, fp masks for image borders, single barrier before the 8-way reduce.
// ---------------------------------------------------------------------------
__global__ __launch_bounds__(256, 2) void iter_kernel(
    int src_sel,                    // 0: read d_bufA, 1: read d_bufB
    float* __restrict__ dst_ext,    // if non-null, write here (final iter)
    const float* __restrict__ guid,
    const float* __restrict__ sparse)
{
    extern __shared__ float smem[];
    float* sg   = smem + 16;                     // [CC][NROWS][SROW]
    float* sd   = sg + SG_FLOATS;                // [NROWS][SROW]
    float* sout = sd + SD_FLOATS;                // [CC][BANDH][TX]
    const unsigned mbar = (unsigned)__cvta_generic_to_shared(smem);

    const int tid  = threadIdx.x;
    const int lane = tid & 31;
    const int c    = tid >> 5;             // warp == channel
    const int bid  = blockIdx.x;
    const int xc   = bid & 3;
    const int yb   = (bid >> 2) & 31;
    const int b    = bid >> 7;
    const int x0   = xc * TX;
    const int y0   = yb * BANDH;

    const float* dsrc  = src_sel ? d_bufB : d_bufA;
    float*       ddst  = dst_ext ? dst_ext : (src_sel ? d_bufA : d_bufB);
    const float* dsb   = dsrc   + (size_t)b * PLANE;
    const float* spb   = sparse + (size_t)b * PLANE;
    float*       ddb   = ddst   + (size_t)b * PLANE;
    const float* gbase = guid   + ((size_t)(b * CC)) * PLANE;

    // tile-uniform copy geometry (clip at image edges; stale cols zeroed)
    const bool left  = (x0 == 0);
    const bool right = (x0 + TX >= WW);
    const int  src_c0  = left ? 0 : (x0 - 4);
    const int  dst_off = left ? 4 : 0;
    const unsigned cpy_b = (left || right) ? 528u : 544u;

    if (tid == 0) {
        asm volatile("mbarrier.init.shared.b64 [%0], %1;"
                     :: "r"(mbar), "r"(1u) : "memory");
    }
    __syncthreads();
    if (tid == 0) {
        asm volatile("mbarrier.arrive.expect_tx.shared.b64 _, [%0], %1;"
                     :: "r"(mbar), "r"(90u * cpy_b) : "memory");
    }
    __syncthreads();

    // zero the 4 stale columns per row on clipped tiles (NaN-safe masking)
    if ((left || right) && tid < 90) {
        const int stale = left ? 0 : 132;
        float* rowp = (tid < 80)
            ? sg + ((tid / 10) * NROWS + (tid % 10)) * SROW
            : sd + (tid - 80) * SROW;
        *reinterpret_cast<float4*>(rowp + stale) = make_float4(0.f, 0.f, 0.f, 0.f);
    }

    // issue 90 bulk row copies (80 g rows + 10 d rows), one instruction each
    if (tid < 90) {
        const int cc  = tid / 10;          // 0..7 = g channel, 8 = d band
        const int r   = tid % 10;
        const int ry  = y0 - 1 + r;
        const int ryc = (ry < 0) ? 0 : ((ry >= HH) ? (HH - 1) : ry);
        const float* src;
        float* dstp;
        if (cc < CC) {
            src  = gbase + (size_t)cc * PLANE + (size_t)ryc * WW + src_c0;
            dstp = sg + (cc * NROWS + r) * SROW + dst_off;
        } else {
            src  = dsb + (size_t)ryc * WW + src_c0;
            dstp = sd + r * SROW + dst_off;
        }
        const unsigned dsm = (unsigned)__cvta_generic_to_shared(dstp);
        asm volatile(
            "cp.async.bulk.shared::cta.global.mbarrier::complete_tx::bytes "
            "[%0], [%1], %2, [%3];"
            :: "r"(dsm), "l"(src), "r"(cpy_b), "r"(mbar) : "memory");
    }

    // sparse prefetch for the epilogue (overlaps the bulk copies)
    const int ep_row = tid >> 5;
    const int ep_c4  = tid & 31;
    const float4 sp_pre = *reinterpret_cast<const float4*>(
                              spb + (size_t)(y0 + ep_row) * WW + x0 + ep_c4 * 4);

    // wait for all bulk data (parity 0, acquire)
    {
        unsigned done;
        asm volatile(
            "{\n\t.reg .pred p;\n\t"
            "mbarrier.try_wait.parity.acquire.cta.shared::cta.b64 p, [%1], %2;\n\t"
            "selp.b32 %0, 1, 0, p;\n\t}"
            : "=r"(done) : "r"(mbar), "r"(0u) : "memory");
        if (!done) {
            asm volatile(
                "{\n\t.reg .pred P1;\n\t"
                "WAIT_LOOP_%=:\n\t"
                "mbarrier.try_wait.parity.acquire.cta.shared::cta.b64 P1, [%0], %1, 0x989680;\n\t"
                "@P1 bra.uni WAIT_DONE_%=;\n\t"
                "bra.uni WAIT_LOOP_%=;\n\t"
                "WAIT_DONE_%=:\n\t}"
                :: "r"(mbar), "r"(0u) : "memory");
        }
    }

    // ---- this warp's channel: smem-fed rolling mainloop ----
    const float* sgc = sg + c * NROWS * SROW;
    const int sc = 4 + lane * 4;
    const float lm = (lane == 0)  ? ((x0 > 0)       ? 1.f : 0.f) : 1.f;
    const float rm = (lane == 31) ? ((x0 + TX < WW) ? 1.f : 0.f) : 1.f;
    const bool  is_l = (lane == 0);
    const bool  is_r = (lane == 31);

    float4 usp = make_float4(0.f,0.f,0.f,0.f), usc = usp;  // u = g*d rowsums
    float4 gsp = make_float4(0.f,0.f,0.f,0.f), gsc = gsp;  // g rowsums

    #pragma unroll
    for (int i = 0; i < NROWS; i++) {
        const int   ry    = y0 - 1 + i;
        const float vmask = (ry >= 0 && ry < HH) ? 1.f : 0.f;

        const float* gp = sgc + i * SROW;
        const float* dp = sd  + i * SROW;
        const float4 gr = *reinterpret_cast<const float4*>(gp + sc);
        const float4 dr = *reinterpret_cast<const float4*>(dp + sc);
        const float  geL = gp[3],   geR = gp[132];   // broadcast LDS
        const float  deL = dp[3],   deR = dp[132];

        float g_up = __shfl_up_sync  (FULLMASK, gr.w, 1);
        float d_up = __shfl_up_sync  (FULLMASK, dr.w, 1);
        float g_dn = __shfl_down_sync(FULLMASK, gr.x, 1);
        float d_dn = __shfl_down_sync(FULLMASK, dr.x, 1);
        g_up = is_l ? geL : g_up;
        d_up = is_l ? deL : d_up;
        g_dn = is_r ? geR : g_dn;
        d_dn = is_r ? deR : d_dn;

        float4 ga;
        ga.x = fabsf(gr.x) * vmask; ga.y = fabsf(gr.y) * vmask;
        ga.z = fabsf(gr.z) * vmask; ga.w = fabsf(gr.w) * vmask;
        const float gm1 = fabsf(g_up) * (vmask * lm);
        const float gp4 = fabsf(g_dn) * (vmask * rm);

        const float um1 = gm1  * d_up;
        const float u0  = ga.x * dr.x;
        const float u1  = ga.y * dr.y;
        const float u2  = ga.z * dr.z;
        const float u3  = ga.w * dr.w;
        const float up4 = gp4  * d_dn;

        float4 usn, gsn;
        {
            const float t01 = u0 + u1, t12 = u1 + u2, t23 = u2 + u3;
            usn.x = um1 + t01; usn.y = t01 + u2;
            usn.z = t12 + u3;  usn.w = t23 + up4;
            const float s01 = ga.x + ga.y, s12 = ga.y + ga.z, s23 = ga.z + ga.w;
            gsn.x = gm1 + s01;  gsn.y = s01 + ga.z;
            gsn.z = s12 + ga.w; gsn.w = s23 + gp4;
        }

        if (i >= 2) {
            float4 o;
            o.x = __fdividef(usp.x + usc.x + usn.x, gsp.x + gsc.x + gsn.x);
            o.y = __fdividef(usp.y + usc.y + usn.y, gsp.y + gsc.y + gsn.y);
            o.z = __fdividef(usp.z + usc.z + usn.z, gsp.z + gsc.z + gsn.z);
            o.w = __fdividef(usp.w + usc.w + usn.w, gsp.w + gsc.w + gsn.w);
            *reinterpret_cast<float4*>(sout + (c * BANDH + (i - 2)) * TX + lane * 4) = o;
        }
        usp = usc; usc = usn;
        gsp = gsc; gsc = gsn;
    }
    __syncthreads();

    // ---- 8-way max reduce + sparse re-injection + float4 store ----
    {
        const float* so = sout + ep_row * TX + ep_c4 * 4;
        float4 m = *reinterpret_cast<const float4*>(so);
        #pragma unroll
        for (int cc = 1; cc < CC; cc++) {
            const float4 v = *reinterpret_cast<const float4*>(so + cc * BANDH * TX);
            m.x = fmaxf(m.x, v.x); m.y = fmaxf(m.y, v.y);
            m.z = fmaxf(m.z, v.z); m.w = fmaxf(m.w, v.w);
        }
        m.x = (sp_pre.x > 0.f) ? sp_pre.x : m.x;
        m.y = (sp_pre.y > 0.f) ? sp_pre.y : m.y;
        m.z = (sp_pre.z > 0.f) ? sp_pre.z : m.z;
        m.w = (sp_pre.w > 0.f) ? sp_pre.w : m.w;
        *reinterpret_cast<float4*>(ddb + (size_t)(y0 + ep_row) * WW + x0 + ep_c4 * 4) = m;
    }
}

extern "C" void kernel_launch(void* const* d_in, const int* in_sizes, int n_in,
                              void* d_out, int out_size)
{
    const float* guid   = (const float*)d_in[0];
    const float* blur   = (const float*)d_in[1];
    const float* sparse = (const float*)d_in[2];
    float*       out    = (float*)d_out;

    static int attr_done = 0;
    if (!attr_done) {
        cudaFuncSetAttribute(iter_kernel,
                             cudaFuncAttributeMaxDynamicSharedMemorySize,
                             SMEM_BYTES);
        attr_done = 1;
    }

    init_kernel<<<NPIX / 4 / 256, 256>>>(blur, sparse);

    // d0 lives in d_bufA. Even i reads A writes B, odd i reads B writes A.
    for (int i = 0; i < NITER; i++) {
        float* dst_ext = (i == NITER - 1) ? out : nullptr;
        iter_kernel<<<GRID_I, 256, SMEM_BYTES>>>(i & 1, dst_ext, guid, sparse);
    }
}

// round 13
// speedup vs baseline: 1.2062x; 1.0081x over previous
#include <cuda_runtime.h>
#include <cstdint>
#include <math.h>

#define BB 8
#define CC 8
#define HH 256
#define WW 512
#define PLANE (HH*WW)
#define NPIX (BB*PLANE)
#define OUTH 8                              /* output rows per CTA per double-step */
#define D1R (OUTH+2)                        /* 10 intermediate rows */
#define IR  (OUTH+4)                        /* 12 input rows */
#define TX 128
#define SROW 136
#define GRID_I (BB*(HH/OUTH)*(WW/TX))       /* 1024 */
#define NSTEPS 8                            /* 8 double-steps = 16 iters */
#define FULLMASK 0xffffffffu

#define SG  (CC*IR*SROW)                    /* 13056 floats */
#define SD  (IR*SROW)                       /* 1632 */
#define SD1 (D1R*SROW)                      /* 1360 */
#define SMEM_FLOATS (16 + SG + SD + SD1)
#define SMEM_BYTES (SMEM_FLOATS*4)          /* 64,256 B -> 3 CTAs/SM */

// Depth ping-pong scratch (allocation-free).
__device__ float d_bufA[NPIX];              // 4 MB
__device__ float d_bufB[NPIX];              // 4 MB

// ---------------------------------------------------------------------------
// Init: d0 = sparse > 0 ? sparse : blur
// ---------------------------------------------------------------------------
__global__ __launch_bounds__(256) void init_kernel(
    const float* __restrict__ blur,
    const float* __restrict__ sparse)
{
    const int i = blockIdx.x * 256 + threadIdx.x;
    const float4 s = reinterpret_cast<const float4*>(sparse)[i];
    float4 v       = reinterpret_cast<const float4*>(blur)[i];
    v.x = (s.x > 0.f) ? s.x : v.x;
    v.y = (s.y > 0.f) ? s.y : v.y;
    v.z = (s.z > 0.f) ? s.z : v.z;
    v.w = (s.w > 0.f) ? s.w : v.w;
    reinterpret_cast<float4*>(d_bufA)[i] = v;
}

// ---------------------------------------------------------------------------
// TWO CSPN steps per launch. Stage 12-row g(8ch)+d band into smem via bulk
// copies; phase 1 computes the 10-row intermediate d1 (with sparse blend) in
// smem; phase 2 computes the 8x128 output from d1 + smem g. Out-of-image g
// rows/cols are zeroed in smem, so inner loops carry no boundary masks.
// ---------------------------------------------------------------------------
__global__ __launch_bounds__(256, 3) void double_kernel(
    int src_sel,
    float* __restrict__ dst_ext,
    const float* __restrict__ guid,
    const float* __restrict__ sparse)
{
    extern __shared__ float smem[];
    float* sg  = smem + 16;                 // [CC][IR][SROW]
    float* sdm = sg + SG;                   // [IR][SROW]
    float* sd1 = sdm + SD;                  // [D1R][SROW]
    const unsigned mbar = (unsigned)__cvta_generic_to_shared(smem);

    const int tid  = threadIdx.x;
    const int lane = tid & 31;
    const int bid  = blockIdx.x;
    const int xc   = bid & 3;
    const int yb   = (bid >> 2) & 31;
    const int b    = bid >> 7;
    const int x0   = xc * TX;
    const int y0   = yb * OUTH;

    const float* dsrc  = src_sel ? d_bufB : d_bufA;
    float*       ddst  = dst_ext ? dst_ext : (src_sel ? d_bufA : d_bufB);
    const float* dsb   = dsrc   + (size_t)b * PLANE;
    const float* spb   = sparse + (size_t)b * PLANE;
    float*       ddb   = ddst   + (size_t)b * PLANE;
    const float* gbase = guid   + ((size_t)(b * CC)) * PLANE;

    const bool left  = (x0 == 0);
    const bool right = (x0 + TX >= WW);
    const int  src_c0  = left ? 0 : (x0 - 4);
    const int  dst_off = left ? 4 : 0;
    const unsigned cpy_b = (left || right) ? 528u : 544u;
    const int top = (y0 == 0)          ? 2 : 0;
    const int bot = (y0 + OUTH == HH)  ? 2 : 0;

    if (tid == 0)
        asm volatile("mbarrier.init.shared.b64 [%0], %1;" :: "r"(mbar), "r"(1u) : "memory");
    __syncthreads();
    if (tid == 0) {
        const unsigned tx = (unsigned)(CC * (IR - top - bot) + IR) * cpy_b;
        asm volatile("mbarrier.arrive.expect_tx.shared.b64 _, [%0], %1;"
                     :: "r"(mbar), "r"(tx) : "memory");
    }
    __syncthreads();

    // ---- issue bulk row copies: 8 g channels x in-image rows + 12 d rows ----
    if (tid < (CC + 1) * IR) {
        const int cc = tid / IR;            // 0..7 g, 8 = d
        const int r  = tid % IR;
        const int ry = y0 - 2 + r;
        if (cc < CC) {
            if (ry >= 0 && ry < HH) {
                const float* src = gbase + (size_t)cc * PLANE + (size_t)ry * WW + src_c0;
                const unsigned dsm_ = (unsigned)__cvta_generic_to_shared(
                                          sg + (cc * IR + r) * SROW + dst_off);
                asm volatile(
                    "cp.async.bulk.shared::cta.global.mbarrier::complete_tx::bytes "
                    "[%0], [%1], %2, [%3];"
                    :: "r"(dsm_), "l"(src), "r"(cpy_b), "r"(mbar) : "memory");
            }
        } else {
            const int ryc = (ry < 0) ? 0 : ((ry >= HH) ? (HH - 1) : ry);
            const float* src = dsb + (size_t)ryc * WW + src_c0;
            const unsigned dsm_ = (unsigned)__cvta_generic_to_shared(
                                      sdm + r * SROW + dst_off);
            asm volatile(
                "cp.async.bulk.shared::cta.global.mbarrier::complete_tx::bytes "
                "[%0], [%1], %2, [%3];"
                :: "r"(dsm_), "l"(src), "r"(cpy_b), "r"(mbar) : "memory");
        }
    }

    // ---- zero out-of-image g rows (band top/bottom) ----
    if (top + bot) {
        const int per = (top + bot) * 34;
        const int nz  = CC * per;
        for (int idx = tid; idx < nz; idx += 256) {
            const int ch  = idx / per;
            const int rem = idx - ch * per;
            const int ri  = rem / 34;
            const int j   = rem - ri * 34;
            const int r   = (ri < top) ? ri : (IR - bot + (ri - top));
            *reinterpret_cast<float4*>(sg + (ch * IR + r) * SROW + 4 * j) =
                make_float4(0.f, 0.f, 0.f, 0.f);
        }
    }
    // ---- zero out-of-image halo cols (left/right tiles); disjoint from copies --
    if ((left || right) && tid < (CC + 1) * IR) {
        const int zc = left ? 0 : 132;
        const int cc = tid / IR;
        const int r  = tid % IR;
        float* p = (cc < CC) ? (sg + (cc * IR + r) * SROW + zc)
                             : (sdm + r * SROW + zc);
        *reinterpret_cast<float4*>(p) = make_float4(0.f, 0.f, 0.f, 0.f);
    }

    // ---- wait for bulk data (parity 0, acquire) ----
    {
        unsigned done;
        asm volatile(
            "{\n\t.reg .pred p;\n\t"
            "mbarrier.try_wait.parity.acquire.cta.shared::cta.b64 p, [%1], %2;\n\t"
            "selp.b32 %0, 1, 0, p;\n\t}"
            : "=r"(done) : "r"(mbar), "r"(0u) : "memory");
        if (!done) {
            asm volatile(
                "{\n\t.reg .pred P1;\n\t"
                "WAIT_LOOP_%=:\n\t"
                "mbarrier.try_wait.parity.acquire.cta.shared::cta.b64 P1, [%0], %1, 0x989680;\n\t"
                "@P1 bra.uni WAIT_DONE_%=;\n\t"
                "bra.uni WAIT_LOOP_%=;\n\t"
                "WAIT_DONE_%=:\n\t}"
                :: "r"(mbar), "r"(0u) : "memory");
        }
    }
    __syncthreads();   // also covers visibility of the zeroed regions

    // ================= PHASE 1: compute d1 (10 rows x 136 cols) =============
    #pragma unroll 1
    for (int it = 0; it < 2; it++) {
        const int idx = tid + it * 256;
        if (idx < D1R * 34) {
            const int r1 = idx / 34;
            const int j  = idx - r1 * 34;
            const int c0 = 4 * j;
            const int cm = (c0 == 0) ? 0 : (c0 - 1);
            const int cp = (c0 + 4 > 135) ? 135 : (c0 + 4);

            float dc[3][4], dlf[3], drt[3];
            #pragma unroll
            for (int rr = 0; rr < 3; rr++) {
                const float* dp = sdm + (r1 + rr) * SROW;
                const float4 v = *reinterpret_cast<const float4*>(dp + c0);
                dc[rr][0] = v.x; dc[rr][1] = v.y; dc[rr][2] = v.z; dc[rr][3] = v.w;
                dlf[rr] = dp[cm]; drt[rr] = dp[cp];
            }
            float mx0 = 0.f, mx1 = 0.f, mx2 = 0.f, mx3 = 0.f;
            #pragma unroll
            for (int ch = 0; ch < CC; ch++) {
                const float* gb = sg + ch * IR * SROW;
                float n0=0.f,n1=0.f,n2=0.f,n3=0.f, e0=0.f,e1=0.f,e2=0.f,e3=0.f;
                #pragma unroll
                for (int rr = 0; rr < 3; rr++) {
                    const float* gp = gb + (r1 + rr) * SROW;
                    const float4 gv = *reinterpret_cast<const float4*>(gp + c0);
                    const float g0 = fabsf(gv.x), g1 = fabsf(gv.y);
                    const float g2 = fabsf(gv.z), g3 = fabsf(gv.w);
                    const float gl = fabsf(gp[cm]), gr_ = fabsf(gp[cp]);
                    const float s01 = g0 + g1, s12 = g1 + g2, s23 = g2 + g3;
                    e0 += gl + s01; e1 += s01 + g2; e2 += s12 + g3; e3 += s23 + gr_;
                    const float ul = gl * dlf[rr], u0 = g0 * dc[rr][0];
                    const float u1 = g1 * dc[rr][1], u2 = g2 * dc[rr][2];
                    const float u3 = g3 * dc[rr][3], ur = gr_ * drt[rr];
                    const float t01 = u0 + u1, t12 = u1 + u2, t23 = u2 + u3;
                    n0 += ul + t01; n1 += t01 + u2; n2 += t12 + u3; n3 += t23 + ur;
                }
                mx0 = fmaxf(mx0, __fdividef(n0, e0));
                mx1 = fmaxf(mx1, __fdividef(n1, e1));
                mx2 = fmaxf(mx2, __fdividef(n2, e2));
                mx3 = fmaxf(mx3, __fdividef(n3, e3));
            }
            // masks (image validity) + sparse re-injection
            const int  yrow = y0 - 1 + r1;
            const bool rv   = (yrow >= 0) && (yrow < HH);
            const int  yrc  = (yrow < 0) ? 0 : ((yrow >= HH) ? (HH - 1) : yrow);
            const int  xb   = x0 - 4 + c0;
            const int  xbc  = (xb < 0) ? 0 : ((xb > WW - 4) ? (WW - 4) : xb);
            const float4 s  = *reinterpret_cast<const float4*>(spb + (size_t)yrc * WW + xbc);
            float4 o;
            o.x = (rv && xb     >= 0 && xb     < WW) ? ((s.x > 0.f) ? s.x : mx0) : 0.f;
            o.y = (rv && xb + 1 >= 0 && xb + 1 < WW) ? ((s.y > 0.f) ? s.y : mx1) : 0.f;
            o.z = (rv && xb + 2 >= 0 && xb + 2 < WW) ? ((s.z > 0.f) ? s.z : mx2) : 0.f;
            o.w = (rv && xb + 3 >= 0 && xb + 3 < WW) ? ((s.w > 0.f) ? s.w : mx3) : 0.f;
            *reinterpret_cast<float4*>(sd1 + r1 * SROW + c0) = o;
        }
    }
    __syncthreads();

    // ================= PHASE 2: output 8 rows x 128 cols =====================
    {
        const int k  = tid >> 5;            // warp = output row
        const int sc = 4 + lane * 4;
        const int cm = sc - 1, cp = sc + 4;

        float dc[3][4], dlf[3], drt[3];
        #pragma unroll
        for (int rr = 0; rr < 3; rr++) {
            const float* dp = sd1 + (k + rr) * SROW;
            const float4 v = *reinterpret_cast<const float4*>(dp + sc);
            dc[rr][0] = v.x; dc[rr][1] = v.y; dc[rr][2] = v.z; dc[rr][3] = v.w;
            dlf[rr] = dp[cm]; drt[rr] = dp[cp];
        }
        float mx0 = 0.f, mx1 = 0.f, mx2 = 0.f, mx3 = 0.f;
        #pragma unroll
        for (int ch = 0; ch < CC; ch++) {
            const float* gb = sg + ch * IR * SROW;
            float n0=0.f,n1=0.f,n2=0.f,n3=0.f, e0=0.f,e1=0.f,e2=0.f,e3=0.f;
            #pragma unroll
            for (int rr = 0; rr < 3; rr++) {
                const float* gp = gb + (k + 1 + rr) * SROW;
                const float4 gv = *reinterpret_cast<const float4*>(gp + sc);
                const float g0 = fabsf(gv.x), g1 = fabsf(gv.y);
                const float g2 = fabsf(gv.z), g3 = fabsf(gv.w);
                const float gl = fabsf(gp[cm]), gr_ = fabsf(gp[cp]);
                const float s01 = g0 + g1, s12 = g1 + g2, s23 = g2 + g3;
                e0 += gl + s01; e1 += s01 + g2; e2 += s12 + g3; e3 += s23 + gr_;
                const float ul = gl * dlf[rr], u0 = g0 * dc[rr][0];
                const float u1 = g1 * dc[rr][1], u2 = g2 * dc[rr][2];
                const float u3 = g3 * dc[rr][3], ur = gr_ * drt[rr];
                const float t01 = u0 + u1, t12 = u1 + u2, t23 = u2 + u3;
                n0 += ul + t01; n1 += t01 + u2; n2 += t12 + u3; n3 += t23 + ur;
            }
            mx0 = fmaxf(mx0, __fdividef(n0, e0));
            mx1 = fmaxf(mx1, __fdividef(n1, e1));
            mx2 = fmaxf(mx2, __fdividef(n2, e2));
            mx3 = fmaxf(mx3, __fdividef(n3, e3));
        }
        const size_t off = (size_t)(y0 + k) * WW + x0 + lane * 4;
        const float4 s = *reinterpret_cast<const float4*>(spb + off);
        float4 o;
        o.x = (s.x > 0.f) ? s.x : mx0;
        o.y = (s.y > 0.f) ? s.y : mx1;
        o.z = (s.z > 0.f) ? s.z : mx2;
        o.w = (s.w > 0.f) ? s.w : mx3;
        *reinterpret_cast<float4*>(ddb + off) = o;
    }
}

extern "C" void kernel_launch(void* const* d_in, const int* in_sizes, int n_in,
                              void* d_out, int out_size)
{
    const float* guid   = (const float*)d_in[0];
    const float* blur   = (const float*)d_in[1];
    const float* sparse = (const float*)d_in[2];
    float*       out    = (float*)d_out;

    static int attr_done = 0;
    if (!attr_done) {
        cudaFuncSetAttribute(double_kernel,
                             cudaFuncAttributeMaxDynamicSharedMemorySize,
                             SMEM_BYTES);
        attr_done = 1;
    }

    init_kernel<<<NPIX / 4 / 256, 256>>>(blur, sparse);

    // d0 in d_bufA; each launch performs 2 CSPN steps. 8 launches = 16 steps.
    for (int i = 0; i < NSTEPS; i++) {
        float* dst_ext = (i == NSTEPS - 1) ? out : nullptr;
        double_kernel<<<GRID_I, 256, SMEM_BYTES>>>(i & 1, dst_ext, guid, sparse);
    }
}

// round 14
// speedup vs baseline: 1.2175x; 1.0094x over previous
#include <cuda_runtime.h>
#include <cstdint>
#include <math.h>

#define BB 8
#define CC 8
#define HH 256
#define WW 512
#define PLANE (HH*WW)
#define NPIX (BB*PLANE)
#define OUTH 8                              /* output rows per CTA per double-step */
#define D1R (OUTH+2)                        /* 10 intermediate rows */
#define IR  (OUTH+4)                        /* 12 input rows */
#define TX 128
#define SROW 136
#define GRID_I (BB*(HH/OUTH)*(WW/TX))       /* 1024 */
#define NSTEPS 8                            /* 8 double-steps = 16 iters */
#define FULLMASK 0xffffffffu

#define SG  (CC*IR*SROW)                    /* 13056 floats */
#define SD  (IR*SROW)                       /* 1632 */
#define SD1 (D1R*SROW)                      /* 1360 */
#define SMEM_FLOATS (16 + SG + SD + SD1)
#define SMEM_BYTES (SMEM_FLOATS*4)          /* 64,256 B -> 3 CTAs/SM */

// Depth ping-pong scratch (allocation-free).
__device__ float d_bufA[NPIX];              // 4 MB
__device__ float d_bufB[NPIX];              // 4 MB

// ---------------------------------------------------------------------------
// Init: d0 = sparse > 0 ? sparse : blur
// ---------------------------------------------------------------------------
__global__ __launch_bounds__(256) void init_kernel(
    const float* __restrict__ blur,
    const float* __restrict__ sparse)
{
    const int i = blockIdx.x * 256 + threadIdx.x;
    const float4 s = reinterpret_cast<const float4*>(sparse)[i];
    float4 v       = reinterpret_cast<const float4*>(blur)[i];
    v.x = (s.x > 0.f) ? s.x : v.x;
    v.y = (s.y > 0.f) ? s.y : v.y;
    v.z = (s.z > 0.f) ? s.z : v.z;
    v.w = (s.w > 0.f) ? s.w : v.w;
    reinterpret_cast<float4*>(d_bufA)[i] = v;
}

// ---------------------------------------------------------------------------
// TWO CSPN steps per launch, warp-per-row phases with shfl halos (no bank
// conflicts). Bulk copies stage 12-row g(8ch)+d band; phase 1 computes 10-row
// d1 in smem; phase 2 emits the 8x128 output. Out-of-image smem pre-zeroed.
// ---------------------------------------------------------------------------
__global__ __launch_bounds__(256, 3) void double_kernel(
    int src_sel,
    float* __restrict__ dst_ext,
    const float* __restrict__ guid,
    const float* __restrict__ sparse)
{
    extern __shared__ float smem[];
    float* sg  = smem + 16;                 // [CC][IR][SROW]
    float* sdm = sg + SG;                   // [IR][SROW]
    float* sd1 = sdm + SD;                  // [D1R][SROW]
    const unsigned mbar = (unsigned)__cvta_generic_to_shared(smem);

    const int tid  = threadIdx.x;
    const int lane = tid & 31;
    const int wid  = tid >> 5;
    const int bid  = blockIdx.x;
    const int xc   = bid & 3;
    const int yb   = (bid >> 2) & 31;
    const int b    = bid >> 7;
    const int x0   = xc * TX;
    const int y0   = yb * OUTH;

    const float* dsrc  = src_sel ? d_bufB : d_bufA;
    float*       ddst  = dst_ext ? dst_ext : (src_sel ? d_bufA : d_bufB);
    const float* dsb   = dsrc   + (size_t)b * PLANE;
    const float* spb   = sparse + (size_t)b * PLANE;
    float*       ddb   = ddst   + (size_t)b * PLANE;
    const float* gbase = guid   + ((size_t)(b * CC)) * PLANE;

    const bool left  = (x0 == 0);
    const bool right = (x0 + TX >= WW);
    const int  src_c0  = left ? 0 : (x0 - 4);
    const int  dst_off = left ? 4 : 0;
    const unsigned cpy_b = (left || right) ? 528u : 544u;
    const int top = (y0 == 0)          ? 2 : 0;
    const int bot = (y0 + OUTH == HH)  ? 2 : 0;

    if (tid == 0)
        asm volatile("mbarrier.init.shared.b64 [%0], %1;" :: "r"(mbar), "r"(1u) : "memory");
    __syncthreads();
    if (tid == 0) {
        const unsigned tx = (unsigned)(CC * (IR - top - bot) + IR) * cpy_b;
        asm volatile("mbarrier.arrive.expect_tx.shared.b64 _, [%0], %1;"
                     :: "r"(mbar), "r"(tx) : "memory");
    }
    __syncthreads();

    // ---- issue bulk row copies: 8 g channels x in-image rows + 12 d rows ----
    if (tid < (CC + 1) * IR) {
        const int cc = tid / IR;
        const int r  = tid % IR;
        const int ry = y0 - 2 + r;
        if (cc < CC) {
            if (ry >= 0 && ry < HH) {
                const float* src = gbase + (size_t)cc * PLANE + (size_t)ry * WW + src_c0;
                const unsigned dsm_ = (unsigned)__cvta_generic_to_shared(
                                          sg + (cc * IR + r) * SROW + dst_off);
                asm volatile(
                    "cp.async.bulk.shared::cta.global.mbarrier::complete_tx::bytes "
                    "[%0], [%1], %2, [%3];"
                    :: "r"(dsm_), "l"(src), "r"(cpy_b), "r"(mbar) : "memory");
            }
        } else {
            const int ryc = (ry < 0) ? 0 : ((ry >= HH) ? (HH - 1) : ry);
            const float* src = dsb + (size_t)ryc * WW + src_c0;
            const unsigned dsm_ = (unsigned)__cvta_generic_to_shared(
                                      sdm + r * SROW + dst_off);
            asm volatile(
                "cp.async.bulk.shared::cta.global.mbarrier::complete_tx::bytes "
                "[%0], [%1], %2, [%3];"
                :: "r"(dsm_), "l"(src), "r"(cpy_b), "r"(mbar) : "memory");
        }
    }

    // ---- zero out-of-image g rows (band top/bottom) ----
    if (top + bot) {
        const int per = (top + bot) * 34;
        const int nz  = CC * per;
        for (int idx = tid; idx < nz; idx += 256) {
            const int ch  = idx / per;
            const int rem = idx - ch * per;
            const int ri  = rem / 34;
            const int j   = rem - ri * 34;
            const int r   = (ri < top) ? ri : (IR - bot + (ri - top));
            *reinterpret_cast<float4*>(sg + (ch * IR + r) * SROW + 4 * j) =
                make_float4(0.f, 0.f, 0.f, 0.f);
        }
    }
    // ---- zero out-of-image halo cols (left/right tiles) ----
    if ((left || right) && tid < (CC + 1) * IR) {
        const int zc = left ? 0 : 132;
        const int cc = tid / IR;
        const int r  = tid % IR;
        float* p = (cc < CC) ? (sg + (cc * IR + r) * SROW + zc)
                             : (sdm + r * SROW + zc);
        *reinterpret_cast<float4*>(p) = make_float4(0.f, 0.f, 0.f, 0.f);
    }

    // ---- wait for bulk data ----
    {
        unsigned done;
        asm volatile(
            "{\n\t.reg .pred p;\n\t"
            "mbarrier.try_wait.parity.acquire.cta.shared::cta.b64 p, [%1], %2;\n\t"
            "selp.b32 %0, 1, 0, p;\n\t}"
            : "=r"(done) : "r"(mbar), "r"(0u) : "memory");
        if (!done) {
            asm volatile(
                "{\n\t.reg .pred P1;\n\t"
                "WAIT_LOOP_%=:\n\t"
                "mbarrier.try_wait.parity.acquire.cta.shared::cta.b64 P1, [%0], %1, 0x989680;\n\t"
                "@P1 bra.uni WAIT_DONE_%=;\n\t"
                "bra.uni WAIT_LOOP_%=;\n\t"
                "WAIT_DONE_%=:\n\t}"
                :: "r"(mbar), "r"(0u) : "memory");
        }
    }
    __syncthreads();

    const int  sc   = 4 + lane * 4;
    const bool is_l = (lane == 0);
    const bool is_r = (lane == 31);

    // ================= PHASE 1: d1 rows via warp-per-row + shfl halos ========
    #pragma unroll
    for (int r1 = wid; r1 < D1R; r1 += 8) {
        float4 dv[3]; float dlf[3], drt[3];
        #pragma unroll
        for (int rr = 0; rr < 3; rr++) {
            const float* dp = sdm + (r1 + rr) * SROW;
            dv[rr] = *reinterpret_cast<const float4*>(dp + sc);
            const float up = __shfl_up_sync  (FULLMASK, dv[rr].w, 1);
            const float dn = __shfl_down_sync(FULLMASK, dv[rr].x, 1);
            dlf[rr] = is_l ? dp[3]   : up;
            drt[rr] = is_r ? dp[132] : dn;
        }
        float mx0 = 0.f, mx1 = 0.f, mx2 = 0.f, mx3 = 0.f;
        #pragma unroll
        for (int ch = 0; ch < CC; ch++) {
            const float* gb = sg + ch * IR * SROW;
            float n0=0.f,n1=0.f,n2=0.f,n3=0.f, e0=0.f,e1=0.f,e2=0.f,e3=0.f;
            #pragma unroll
            for (int rr = 0; rr < 3; rr++) {
                const float* gp = gb + (r1 + rr) * SROW;
                const float4 gv = *reinterpret_cast<const float4*>(gp + sc);
                const float gup = __shfl_up_sync  (FULLMASK, gv.w, 1);
                const float gdn = __shfl_down_sync(FULLMASK, gv.x, 1);
                const float gl  = fabsf(is_l ? gp[3]   : gup);
                const float gr_ = fabsf(is_r ? gp[132] : gdn);
                const float g0 = fabsf(gv.x), g1 = fabsf(gv.y);
                const float g2 = fabsf(gv.z), g3 = fabsf(gv.w);
                const float s01 = g0 + g1, s12 = g1 + g2, s23 = g2 + g3;
                e0 += gl + s01; e1 += s01 + g2; e2 += s12 + g3; e3 += s23 + gr_;
                const float ul = gl * dlf[rr], u0 = g0 * dv[rr].x;
                const float u1 = g1 * dv[rr].y, u2 = g2 * dv[rr].z;
                const float u3 = g3 * dv[rr].w, ur = gr_ * drt[rr];
                const float t01 = u0 + u1, t12 = u1 + u2, t23 = u2 + u3;
                n0 += ul + t01; n1 += t01 + u2; n2 += t12 + u3; n3 += t23 + ur;
            }
            mx0 = fmaxf(mx0, __fdividef(n0, e0));
            mx1 = fmaxf(mx1, __fdividef(n1, e1));
            mx2 = fmaxf(mx2, __fdividef(n2, e2));
            mx3 = fmaxf(mx3, __fdividef(n3, e3));
        }
        const int  yrow = y0 - 1 + r1;
        const bool rv   = (yrow >= 0) && (yrow < HH);
        const int  yrc  = (yrow < 0) ? 0 : ((yrow >= HH) ? (HH - 1) : yrow);
        const float4 s  = *reinterpret_cast<const float4*>(
                              spb + (size_t)yrc * WW + x0 + lane * 4);
        float4 o;
        o.x = rv ? ((s.x > 0.f) ? s.x : mx0) : 0.f;
        o.y = rv ? ((s.y > 0.f) ? s.y : mx1) : 0.f;
        o.z = rv ? ((s.z > 0.f) ? s.z : mx2) : 0.f;
        o.w = rv ? ((s.w > 0.f) ? s.w : mx3) : 0.f;
        *reinterpret_cast<float4*>(sd1 + r1 * SROW + sc) = o;
    }

    // ---- tail: d1 edge cols (smem cols 3 and 132), rows 0..9 ----
    if (tid < 2 * D1R) {
        const int r1   = tid >> 1;
        const int colc = (tid & 1) ? 132 : 3;
        float mx = 0.f;
        #pragma unroll
        for (int ch = 0; ch < CC; ch++) {
            const float* gb = sg + ch * IR * SROW;
            float n = 0.f, e = 0.f;
            #pragma unroll
            for (int rr = 0; rr < 3; rr++) {
                const float* gp = gb  + (r1 + rr) * SROW;
                const float* dp = sdm + (r1 + rr) * SROW;
                #pragma unroll
                for (int dc = -1; dc <= 1; dc++) {
                    const float g = fabsf(gp[colc + dc]);
                    e += g;
                    n += g * dp[colc + dc];
                }
            }
            mx = fmaxf(mx, __fdividef(n, e));
        }
        const int  yrow = y0 - 1 + r1;
        const bool rv   = (yrow >= 0) && (yrow < HH);
        const int  yrc  = (yrow < 0) ? 0 : ((yrow >= HH) ? (HH - 1) : yrow);
        const int  gx   = x0 - 4 + colc;
        const bool xv   = (gx >= 0) && (gx < WW);
        const int  gxc  = (gx < 0) ? 0 : ((gx >= WW) ? (WW - 1) : gx);
        const float s   = spb[(size_t)yrc * WW + gxc];
        sd1[r1 * SROW + colc] = (rv && xv) ? ((s > 0.f) ? s : mx) : 0.f;
    }
    __syncthreads();

    // ================= PHASE 2: output rows via warp-per-row =================
    {
        const int k = wid;
        float4 dv[3]; float dlf[3], drt[3];
        #pragma unroll
        for (int rr = 0; rr < 3; rr++) {
            const float* dp = sd1 + (k + rr) * SROW;
            dv[rr] = *reinterpret_cast<const float4*>(dp + sc);
            const float up = __shfl_up_sync  (FULLMASK, dv[rr].w, 1);
            const float dn = __shfl_down_sync(FULLMASK, dv[rr].x, 1);
            dlf[rr] = is_l ? dp[3]   : up;
            drt[rr] = is_r ? dp[132] : dn;
        }
        float mx0 = 0.f, mx1 = 0.f, mx2 = 0.f, mx3 = 0.f;
        #pragma unroll
        for (int ch = 0; ch < CC; ch++) {
            const float* gb = sg + ch * IR * SROW;
            float n0=0.f,n1=0.f,n2=0.f,n3=0.f, e0=0.f,e1=0.f,e2=0.f,e3=0.f;
            #pragma unroll
            for (int rr = 0; rr < 3; rr++) {
                const float* gp = gb + (k + 1 + rr) * SROW;
                const float4 gv = *reinterpret_cast<const float4*>(gp + sc);
                const float gup = __shfl_up_sync  (FULLMASK, gv.w, 1);
                const float gdn = __shfl_down_sync(FULLMASK, gv.x, 1);
                const float gl  = fabsf(is_l ? gp[3]   : gup);
                const float gr_ = fabsf(is_r ? gp[132] : gdn);
                const float g0 = fabsf(gv.x), g1 = fabsf(gv.y);
                const float g2 = fabsf(gv.z), g3 = fabsf(gv.w);
                const float s01 = g0 + g1, s12 = g1 + g2, s23 = g2 + g3;
                e0 += gl + s01; e1 += s01 + g2; e2 += s12 + g3; e3 += s23 + gr_;
                const float ul = gl * dlf[rr], u0 = g0 * dv[rr].x;
                const float u1 = g1 * dv[rr].y, u2 = g2 * dv[rr].z;
                const float u3 = g3 * dv[rr].w, ur = gr_ * drt[rr];
                const float t01 = u0 + u1, t12 = u1 + u2, t23 = u2 + u3;
                n0 += ul + t01; n1 += t01 + u2; n2 += t12 + u3; n3 += t23 + ur;
            }
            mx0 = fmaxf(mx0, __fdividef(n0, e0));
            mx1 = fmaxf(mx1, __fdividef(n1, e1));
            mx2 = fmaxf(mx2, __fdividef(n2, e2));
            mx3 = fmaxf(mx3, __fdividef(n3, e3));
        }
        const size_t off = (size_t)(y0 + k) * WW + x0 + lane * 4;
        const float4 s = *reinterpret_cast<const float4*>(spb + off);
        float4 o;
        o.x = (s.x > 0.f) ? s.x : mx0;
        o.y = (s.y > 0.f) ? s.y : mx1;
        o.z = (s.z > 0.f) ? s.z : mx2;
        o.w = (s.w > 0.f) ? s.w : mx3;
        *reinterpret_cast<float4*>(ddb + off) = o;
    }
}

extern "C" void kernel_launch(void* const* d_in, const int* in_sizes, int n_in,
                              void* d_out, int out_size)
{
    const float* guid   = (const float*)d_in[0];
    const float* blur   = (const float*)d_in[1];
    const float* sparse = (const float*)d_in[2];
    float*       out    = (float*)d_out;

    static int attr_done = 0;
    if (!attr_done) {
        cudaFuncSetAttribute(double_kernel,
                             cudaFuncAttributeMaxDynamicSharedMemorySize,
                             SMEM_BYTES);
        attr_done = 1;
    }

    init_kernel<<<NPIX / 4 / 256, 256>>>(blur, sparse);

    // d0 in d_bufA; each launch performs 2 CSPN steps. 8 launches = 16 steps.
    for (int i = 0; i < NSTEPS; i++) {
        float* dst_ext = (i == NSTEPS - 1) ? out : nullptr;
        double_kernel<<<GRID_I, 256, SMEM_BYTES>>>(i & 1, dst_ext, guid, sparse);
    }
}